// round 16
// baseline (speedup 1.0000x reference)
#include <cuda_runtime.h>
#include <cuda_fp16.h>
#include <math.h>

#define B_   64
#define S_   4096
#define DEC_ 512
#define ENC_ 256
#define MT   128                                       // rows per k_scores tile
#define NSM  148

// ---------------- device scratch (allocation-free rule) ----------------
__device__ float2 g_dw[B_ * ENC_];                    // (dpe, Wa) per (b,f)
__device__ float  g_scores[B_ * S_];                  // compacted e = exp(score)
__device__ int    g_idx[B_ * S_];                     // unmasked index lists
__device__ int    g_cnt[B_];                          // unmasked counts
__device__ float  g_cpart[(size_t)B_ * 32 * ENC_];    // per-tile ctx partials
__device__ float  g_esum[B_ * 32];                    // per-tile sum of e
// We^T fp16 per K-chunk of 64, LDSM-native block layout:
//   addr(n,kc) = (g*4+ks)*512 + h16*256 + (n&15)*16 + (kc&7)*2
__device__ __align__(16) unsigned char g_Bt[4][32768];

// ---------------- smem layout (bytes), per CTA = 167424 ----------------
#define OB           0u                                // B fp16 full, 128K persistent
#define OAI(buf)     (131072u + (unsigned)(buf) * 16384u) // A fp16 img dbuf (reused: red/sr)
#define ODW          163840u                           // float2[256]
#define OSIDX        165888u                           // int[128]
#define OSE          166400u                           // float[128]
#define SMEM_BYTES   167424u

static __device__ __forceinline__ unsigned s2u(const void* p) {
    unsigned a;
    asm("{ .reg .u64 t; cvta.to.shared.u64 t, %1; cvt.u32.u64 %0, t; }" : "=r"(a) : "l"(p));
    return a;
}
static __device__ __forceinline__ void cp16(unsigned dst, const void* src) {
    asm volatile("cp.async.cg.shared.global [%0], [%1], 16;" :: "r"(dst), "l"(src));
}
#define CP_COMMIT() asm volatile("cp.async.commit_group;" ::: "memory")
#define CP_WAIT0()  asm volatile("cp.async.wait_group 0;" ::: "memory")

#define LDM4(r, addr) \
    asm volatile("ldmatrix.sync.aligned.m8n8.x4.shared.b16 {%0,%1,%2,%3}, [%4];" \
        : "=r"((r)[0]), "=r"((r)[1]), "=r"((r)[2]), "=r"((r)[3]) : "r"(addr))

#define MMAH(d, a, b0, b1) \
    asm volatile("mma.sync.aligned.m16n8k16.row.col.f32.f16.f16.f32 " \
        "{%0,%1,%2,%3}, {%4,%5,%6,%7}, {%8,%9}, {%0,%1,%2,%3};" \
        : "+f"((d)[0]), "+f"((d)[1]), "+f"((d)[2]), "+f"((d)[3]) \
        : "r"((a)[0]), "r"((a)[1]), "r"((a)[2]), "r"((a)[3]), "r"(b0), "r"(b1))

static __device__ __forceinline__ float tanha(float x) {
    float y;
    asm("tanh.approx.f32 %0, %1;" : "=f"(y) : "f"(x));
    return y;
}

// ---------------------------------------------------------------------------
// k_pre: 3 roles. blocks 0-63: compact+zero attn; 64-127: We prep;
//        128-191: decproj (4-way ILP)
// ---------------------------------------------------------------------------
__global__ __launch_bounds__(1024)
void k_pre(const int* __restrict__ mask, float* __restrict__ attn,
           const float* __restrict__ We,
           const float* __restrict__ dh, const float* __restrict__ Wd,
           const float* __restrict__ bd, const float* __restrict__ be,
           const float* __restrict__ Wa) {
    const int bid = blockIdx.x, t = threadIdx.x;
    if (bid < 64) {                                   // ---- compact ----
        const int b = bid;
        const int4 m = ((const int4*)(mask + b * S_))[t];
        int c0 = m.x != 0, c1 = m.y != 0, c2 = m.z != 0, c3 = m.w != 0;
        const int ls = c0 + c1 + c2 + c3;
        const int lane = t & 31, wid = t >> 5;
        int ws = ls;
#pragma unroll
        for (int o = 1; o < 32; o <<= 1) {
            int v = __shfl_up_sync(~0u, ws, o);
            if (lane >= o) ws += v;
        }
        __shared__ int wsum[32];
        if (lane == 31) wsum[wid] = ws;
        __syncthreads();
        if (t < 32) {
            int v = wsum[t];
#pragma unroll
            for (int o = 1; o < 32; o <<= 1) {
                int u = __shfl_up_sync(~0u, v, o);
                if (t >= o) v += u;
            }
            wsum[t] = v;
        }
        __syncthreads();
        int p = (wid ? wsum[wid - 1] : 0) + (ws - ls);
        const int s = t * 4;
        int* gi = g_idx + b * S_;
        float* at = attn + b * S_;
        if (c0) gi[p++] = s;     else at[s]     = 0.f;
        if (c1) gi[p++] = s + 1; else at[s + 1] = 0.f;
        if (c2) gi[p++] = s + 2; else at[s + 2] = 0.f;
        if (c3) gi[p++] = s + 3; else at[s + 3] = 0.f;
        if (t == 1023) g_cnt[b] = p;
    } else if (bid < 128) {                           // ---- We prep ----
        const int k = (bid - 64) * 4 + (t >> 8), n = t & 255;
        float v = We[k * 256 + n];
        int ch = k >> 6, kc = k & 63;
        int g = n >> 4, ks = kc >> 4, h16 = (kc >> 3) & 1;
        unsigned addr = (unsigned)((g * 4 + ks) * 512 + h16 * 256 + (n & 15) * 16 +
                                   (kc & 7) * 2);
        *(__half*)&g_Bt[ch][addr] = __float2half_rn(v);
    } else {                                          // ---- decproj ----
        const int b = bid - 128;
        __shared__ float sdh[DEC_];
        __shared__ float part[4][256];
        if (t < DEC_) sdh[t] = dh[b * DEC_ + t];
        __syncthreads();
        const int f = t & 255, q = t >> 8;
        const float* wp = Wd + (q * 128) * 256 + f;
        const float* hp = sdh + q * 128;
        float a0 = 0.f, a1 = 0.f, a2 = 0.f, a3 = 0.f;
#pragma unroll 8
        for (int d = 0; d < 128; d += 4) {
            a0 += hp[d]     * wp[(d)     * 256];
            a1 += hp[d + 1] * wp[(d + 1) * 256];
            a2 += hp[d + 2] * wp[(d + 2) * 256];
            a3 += hp[d + 3] * wp[(d + 3) * 256];
        }
        part[q][f] = (a0 + a1) + (a2 + a3);
        __syncthreads();
        if (t < 256) {
            float v = part[0][t] + part[1][t] + part[2][t] + part[3][t] + bd[t] + be[t];
            g_dw[b * 256 + t] = make_float2(v, Wa[t]);
        }
    }
}

// ---------------------------------------------------------------------------
// k_scores: persistent CTAs; B resident in smem; per tile: 128 rows x 256 cols
// ---------------------------------------------------------------------------
static __device__ __forceinline__ void cvtstore(unsigned dst, float4 v0, float4 v1,
                                                float4 v2, float4 v3) {
    float vf[16] = {v0.x, v0.y, v0.z, v0.w, v1.x, v1.y, v1.z, v1.w,
                    v2.x, v2.y, v2.z, v2.w, v3.x, v3.y, v3.z, v3.w};
    unsigned hu[8];
#pragma unroll
    for (int q = 0; q < 8; ++q) {
        __half2 hp = __halves2half2(__float2half_rn(vf[2 * q]),
                                    __float2half_rn(vf[2 * q + 1]));
        hu[q] = *(unsigned*)&hp;
    }
    asm volatile("st.shared.v4.b32 [%0], {%1,%2,%3,%4};"
                 :: "r"(dst), "r"(hu[0]), "r"(hu[1]), "r"(hu[2]), "r"(hu[3]));
    asm volatile("st.shared.v4.b32 [%0], {%1,%2,%3,%4};"
                 :: "r"(dst + 256u), "r"(hu[4]), "r"(hu[5]), "r"(hu[6]), "r"(hu[7]));
}

__global__ __launch_bounds__(512, 1)
void k_scores(const float* __restrict__ enc) {
    extern __shared__ __align__(16) unsigned char sm[];
    const unsigned sb = s2u(sm);
    const int tid = threadIdx.x, lane = tid & 31, w = tid >> 5;
    const int wr = w & 3, wc = w >> 2;                // 4 row-groups x 4 col-groups

    // ---- Load full B (128KB) once ----
#pragma unroll
    for (int i = 0; i < 16; ++i) {
        int slot = tid + i * 512;                     // 8192 x 16B
        cp16(sb + OB + (unsigned)slot * 16u, &g_Bt[0][0] + slot * 16);
    }
    CP_COMMIT();
    CP_WAIT0();
    __syncthreads();

    // per-lane ldmatrix offsets within a 512B block
    const unsigned a_lo = (unsigned)((lane & 15) * 16 + (lane >> 4) * 256);
    const unsigned b_lo = (unsigned)((lane & 7) * 16 + ((lane >> 4) & 1) * 128 +
                                     ((lane >> 3) & 1) * 256);
    const int r_ = tid >> 2, s_ = tid & 3;            // A slice: row r_, ks s_

    for (int gidx = blockIdx.x; gidx < B_ * 32; gidx += NSM) {
        const int b = gidx >> 5, tt = gidx & 31;
        const int cnt = g_cnt[b];
        if (tt * MT >= cnt) continue;

        const int j = tt * MT + r_;
        const int row = g_idx[b * S_ + min(j, cnt - 1)];
        const float4* ap = (const float4*)(enc + ((size_t)b * S_ + row) * 256) + s_ * 4;
        const unsigned adst = (unsigned)(((r_ >> 4) * 4 + s_) * 512 + (r_ & 15) * 16);
        if ((tid & 3) == 0) ((int*)(sm + OSIDX))[r_] = row;
        if (tid < 256) ((float2*)(sm + ODW))[tid] = g_dw[b * 256 + tid];

        float4 r0 = ap[0], r1 = ap[1], r2 = ap[2], r3 = ap[3];
        cvtstore(sb + OAI(0) + adst, r0, r1, r2, r3);
        __syncthreads();

        float acc[2][8][4];
#pragma unroll
        for (int mi = 0; mi < 2; ++mi)
#pragma unroll
            for (int ni = 0; ni < 8; ++ni)
#pragma unroll
                for (int q = 0; q < 4; ++q) acc[mi][ni][q] = 0.f;

#pragma unroll 1
        for (int c = 0; c < 4; ++c) {
            const int buf = c & 1;
            if (c < 3) {                              // A(c+1) LDG in flight
                r0 = ap[(c + 1) * 16];
                r1 = ap[(c + 1) * 16 + 1];
                r2 = ap[(c + 1) * 16 + 2];
                r3 = ap[(c + 1) * 16 + 3];
            }
            const unsigned ah_b = sb + OAI(buf) + a_lo;
            const unsigned bh_b = sb + OB + (unsigned)c * 32768u + b_lo;
#pragma unroll
            for (int ks = 0; ks < 4; ++ks) {
                unsigned af[2][4], bh[8][2];
#pragma unroll
                for (int mi = 0; mi < 2; ++mi)
                    LDM4(af[mi], ah_b + (unsigned)(((wr * 2 + mi) * 4 + ks) * 512));
#pragma unroll
                for (int p = 0; p < 4; ++p) {
                    const unsigned blk = (unsigned)(((wc * 4 + p) * 4 + ks) * 512);
                    unsigned r4[4];
                    LDM4(r4, bh_b + blk);
                    bh[2 * p][0] = r4[0]; bh[2 * p][1] = r4[1];
                    bh[2 * p + 1][0] = r4[2]; bh[2 * p + 1][1] = r4[3];
                }
#pragma unroll
                for (int mi = 0; mi < 2; ++mi)
#pragma unroll
                    for (int ni = 0; ni < 8; ++ni)
                        MMAH(acc[mi][ni], af[mi], bh[ni][0], bh[ni][1]);
            }
            if (c < 3) {
                cvtstore(sb + OAI(buf ^ 1) + adst, r0, r1, r2, r3);
                __syncthreads();                      // A-img(c+1) visible
            }
        }

        // ---- Epilogue 1: score partials = sum_cols Wa * tanh(dpe + v) ----
        __syncthreads();                              // A bufs dead: reuse as red/sr
        const float2* sdw = (const float2*)(sm + ODW);
        float* red = (float*)(sm + OAI(0));           // [128][5] padded (2.5KB)
#pragma unroll
        for (int mi = 0; mi < 2; ++mi) {
            float p0 = 0.f, p1 = 0.f;
#pragma unroll
            for (int ni = 0; ni < 8; ++ni) {
                int cc = wc * 64 + ni * 8 + 2 * (lane & 3);
                float2 w0 = sdw[cc], w1 = sdw[cc + 1];
                p0 += w0.y * tanha(acc[mi][ni][0] + w0.x) +
                      w1.y * tanha(acc[mi][ni][1] + w1.x);
                p1 += w0.y * tanha(acc[mi][ni][2] + w0.x) +
                      w1.y * tanha(acc[mi][ni][3] + w1.x);
            }
            p0 += __shfl_xor_sync(~0u, p0, 1); p0 += __shfl_xor_sync(~0u, p0, 2);
            p1 += __shfl_xor_sync(~0u, p1, 1); p1 += __shfl_xor_sync(~0u, p1, 2);
            if ((lane & 3) == 0) {
                int r = wr * 32 + mi * 16 + (lane >> 2);
                red[r * 5 + wc] = p0;
                red[(r + 8) * 5 + wc] = p1;
            }
        }
        __syncthreads();
        // ---- Epilogue 2: e = exp(score) (safe: |score| <= ~13) ----
        float* se = (float*)(sm + OSE);
        if (tid < MT) {
            float s = red[tid * 5] + red[tid * 5 + 1] + red[tid * 5 + 2] + red[tid * 5 + 3];
            float e = (tt * MT + tid < cnt) ? __expf(s) : 0.f;
            se[tid] = e;
            g_scores[b * S_ + tt * MT + tid] = e;
        }
        __syncthreads();
        if (tid < 64) {                               // tile sum of e
            float v = se[tid] + se[tid + 64];
            v += __shfl_xor_sync(~0u, v, 16); v += __shfl_xor_sync(~0u, v, 8);
            v += __shfl_xor_sync(~0u, v, 4);  v += __shfl_xor_sync(~0u, v, 2);
            v += __shfl_xor_sync(~0u, v, 1);
            if (tid == 0 || tid == 32) {
                if (tid == 0) ((float*)(sm + OSE + 512))[0] = v;   // stash warp0 part
            }
        }
        // simpler exact reduce: two halves via red slot
        __syncthreads();
        if (tid == 0) {
            // warp-reduced v above covered lanes of warp0 (rows 0..31 + 64..95);
            // recompute full sum serially-free: use se directly (128 adds by 1 warp)
        }
        if (tid < 32) {
            float v = se[tid] + se[tid + 32] + se[tid + 64] + se[tid + 96];
#pragma unroll
            for (int o = 16; o; o >>= 1) v += __shfl_xor_sync(~0u, v, o);
            if (tid == 0) g_esum[b * 32 + tt] = v;
        }
        // ---- Epilogue 3: ctx partial = sum_r e[r] * enc[row_r,:] (L2 hits) ----
        {
            const int c4 = tid & 63, rg = tid >> 6;   // 8 row-groups of 16
            const int* sidx = (const int*)(sm + OSIDX);
            const float4* e4 = (const float4*)enc + (size_t)b * S_ * 64;
            float4 a4 = make_float4(0.f, 0.f, 0.f, 0.f);
#pragma unroll 4
            for (int i = 0; i < 16; ++i) {
                int r = rg * 16 + i;
                float wv = se[r];
                float4 ev = e4[(size_t)sidx[r] * 64 + c4];
                a4.x += wv * ev.x; a4.y += wv * ev.y; a4.z += wv * ev.z; a4.w += wv * ev.w;
            }
            float4* sr = (float4*)(sm + OAI(0) + 4096u);  // 8KB scratch after red
            sr[rg * 64 + c4] = a4;
            __syncthreads();
            if (tid < 64) {
                float4 o = sr[tid];
#pragma unroll
                for (int g2 = 1; g2 < 8; ++g2) {
                    float4 q = sr[g2 * 64 + tid];
                    o.x += q.x; o.y += q.y; o.z += q.z; o.w += q.w;
                }
                ((float4*)g_cpart)[((size_t)b * 32 + tt) * 64 + tid] = o;
            }
        }
        __syncthreads();                              // epilogue smem dead before next tile
    }
}

// ---------------------------------------------------------------------------
// k_finish: per batch: sum active tiles -> ctx = acc/sum; attn scatter = e/sum
// ---------------------------------------------------------------------------
__global__ __launch_bounds__(1024)
void k_finish(float* __restrict__ ctx, float* __restrict__ attn) {
    const int b = blockIdx.x, t = threadIdx.x;
    const int cnt = g_cnt[b];
    const int ntiles = (cnt + MT - 1) / MT;           // <= 32
    __shared__ float s_e[32];
    __shared__ float s_inv;
    if (t < 32) s_e[t] = (t < ntiles) ? g_esum[b * 32 + t] : 0.f;
    __syncthreads();
    if (t < 32) {
        float v = s_e[t];
#pragma unroll
        for (int o = 16; o; o >>= 1) v += __shfl_xor_sync(~0u, v, o);
        if (t == 0) s_inv = 1.f / v;
    }
    __syncthreads();
    const float inv = s_inv;
    if (t < 256) {
        const float* cp = g_cpart + (size_t)b * 32 * 256 + t;
        float a0 = 0.f, a1 = 0.f, a2 = 0.f, a3 = 0.f;
        int t2 = 0;
        for (; t2 + 4 <= ntiles; t2 += 4) {
            a0 += cp[(t2)     * 256];
            a1 += cp[(t2 + 1) * 256];
            a2 += cp[(t2 + 2) * 256];
            a3 += cp[(t2 + 3) * 256];
        }
        for (; t2 < ntiles; ++t2) a0 += cp[t2 * 256];
        ctx[b * 256 + t] = ((a0 + a1) + (a2 + a3)) * inv;
    }
    for (int j = t; j < cnt; j += 1024)
        attn[b * S_ + g_idx[b * S_ + j]] = g_scores[b * S_ + j] * inv;
}

// ---------------------------------------------------------------------------
extern "C" void kernel_launch(void* const* d_in, const int* in_sizes, int n_in,
                              void* d_out, int out_size) {
    const float* dh   = (const float*)d_in[0];
    const float* enc  = (const float*)d_in[1];
    const int*   mask = (const int*)  d_in[2];
    const float* Wd   = (const float*)d_in[3];
    const float* bd   = (const float*)d_in[4];
    const float* We   = (const float*)d_in[5];
    const float* be   = (const float*)d_in[6];
    const float* Wa   = (const float*)d_in[7];
    // d_in[8] = ba: uniform shift on scores, cancels in softmax

    float* out  = (float*)d_out;
    float* ctx  = out;
    float* attn = out + B_ * ENC_;

    cudaFuncSetAttribute(k_scores, cudaFuncAttributeMaxDynamicSharedMemorySize, SMEM_BYTES);

    k_pre<<<192, 1024>>>(mask, attn, We, dh, Wd, bd, be, Wa);
    k_scores<<<NSM, 512, SMEM_BYTES>>>(enc);
    k_finish<<<B_, 1024>>>(ctx, attn);
}

// round 17
// speedup vs baseline: 1.2602x; 1.2602x over previous
#include <cuda_runtime.h>
#include <cuda_fp16.h>
#include <math.h>

#define B_   64
#define S_   4096
#define DEC_ 512
#define ENC_ 256
#define MT   64                                        // rows per k_scores tile

// ---------------- device scratch (allocation-free rule) ----------------
__device__ float2 g_dw[B_ * ENC_];                    // (dpe, Wa) per (b,f)
__device__ float  g_scores[B_ * S_];                  // compacted e = exp(score)
__device__ int    g_idx[B_ * S_];                     // unmasked index lists
__device__ int    g_cnt[B_];                          // unmasked counts
__device__ float  g_cpart[(size_t)B_ * 64 * ENC_];    // per-tile ctx partials
__device__ float  g_esum[B_ * 64];                    // per-tile sum of e
// We^T fp16 per K-chunk of 32, LDSM-native block layout:
//   addr(n,kc) = (g*2+ks)*512 + h16*256 + (n&15)*16 + (kc&7)*2
__device__ __align__(16) unsigned char g_Bt[8][16384];

// ---------------- smem layout (bytes), per CTA = 109056 (2 CTAs/SM) -------
#define OBI(buf)     ((unsigned)(buf) * 16384u)        // B fp16, 32K dbuf (buf0 reused: red)
#define OAI(buf)     (32768u + (unsigned)(buf) * 4096u) // A fp16 img dbuf (reused: sr)
#define ODW          40960u                            // float2[256]
#define OSE          43008u                            // float[64]
#define OST          43520u                            // fp32 A stage [64][256] = 64K
#define SMEM_BYTES   109056u

static __device__ __forceinline__ unsigned s2u(const void* p) {
    unsigned a;
    asm("{ .reg .u64 t; cvta.to.shared.u64 t, %1; cvt.u32.u64 %0, t; }" : "=r"(a) : "l"(p));
    return a;
}
static __device__ __forceinline__ void cp16(unsigned dst, const void* src) {
    asm volatile("cp.async.cg.shared.global [%0], [%1], 16;" :: "r"(dst), "l"(src));
}
#define CP_COMMIT() asm volatile("cp.async.commit_group;" ::: "memory")
#define CP_WAIT0()  asm volatile("cp.async.wait_group 0;" ::: "memory")

#define LDM4(r, addr) \
    asm volatile("ldmatrix.sync.aligned.m8n8.x4.shared.b16 {%0,%1,%2,%3}, [%4];" \
        : "=r"((r)[0]), "=r"((r)[1]), "=r"((r)[2]), "=r"((r)[3]) : "r"(addr))

#define MMAH(d, a, b0, b1) \
    asm volatile("mma.sync.aligned.m16n8k16.row.col.f32.f16.f16.f32 " \
        "{%0,%1,%2,%3}, {%4,%5,%6,%7}, {%8,%9}, {%0,%1,%2,%3};" \
        : "+f"((d)[0]), "+f"((d)[1]), "+f"((d)[2]), "+f"((d)[3]) \
        : "r"((a)[0]), "r"((a)[1]), "r"((a)[2]), "r"((a)[3]), "r"(b0), "r"(b1))

static __device__ __forceinline__ float tanha(float x) {
    float y;
    asm("tanh.approx.f32 %0, %1;" : "=f"(y) : "f"(x));
    return y;
}

// ---------------------------------------------------------------------------
// k_pre: 3 roles. blocks 0-63: compact+zero attn; 64-127: We prep;
//        128-191: decproj (4-way ILP)
// ---------------------------------------------------------------------------
__global__ __launch_bounds__(1024)
void k_pre(const int* __restrict__ mask, float* __restrict__ attn,
           const float* __restrict__ We,
           const float* __restrict__ dh, const float* __restrict__ Wd,
           const float* __restrict__ bd, const float* __restrict__ be,
           const float* __restrict__ Wa) {
    const int bid = blockIdx.x, t = threadIdx.x;
    if (bid < 64) {                                   // ---- compact ----
        const int b = bid;
        const int4 m = ((const int4*)(mask + b * S_))[t];
        int c0 = m.x != 0, c1 = m.y != 0, c2 = m.z != 0, c3 = m.w != 0;
        const int ls = c0 + c1 + c2 + c3;
        const int lane = t & 31, wid = t >> 5;
        int ws = ls;
#pragma unroll
        for (int o = 1; o < 32; o <<= 1) {
            int v = __shfl_up_sync(~0u, ws, o);
            if (lane >= o) ws += v;
        }
        __shared__ int wsum[32];
        if (lane == 31) wsum[wid] = ws;
        __syncthreads();
        if (t < 32) {
            int v = wsum[t];
#pragma unroll
            for (int o = 1; o < 32; o <<= 1) {
                int u = __shfl_up_sync(~0u, v, o);
                if (t >= o) v += u;
            }
            wsum[t] = v;
        }
        __syncthreads();
        int p = (wid ? wsum[wid - 1] : 0) + (ws - ls);
        const int s = t * 4;
        int* gi = g_idx + b * S_;
        float* at = attn + b * S_;
        if (c0) gi[p++] = s;     else at[s]     = 0.f;
        if (c1) gi[p++] = s + 1; else at[s + 1] = 0.f;
        if (c2) gi[p++] = s + 2; else at[s + 2] = 0.f;
        if (c3) gi[p++] = s + 3; else at[s + 3] = 0.f;
        if (t == 1023) g_cnt[b] = p;
    } else if (bid < 128) {                           // ---- We prep ----
        const int k = (bid - 64) * 4 + (t >> 8), n = t & 255;
        float v = We[k * 256 + n];
        int ch = k >> 5, kc = k & 31;
        int g = n >> 4, ks = kc >> 4, h16 = (kc >> 3) & 1;
        unsigned addr = (unsigned)((g * 2 + ks) * 512 + h16 * 256 + (n & 15) * 16 +
                                   (kc & 7) * 2);
        *(__half*)&g_Bt[ch][addr] = __float2half_rn(v);
    } else {                                          // ---- decproj ----
        const int b = bid - 128;
        __shared__ float sdh[DEC_];
        __shared__ float part[4][256];
        if (t < DEC_) sdh[t] = dh[b * DEC_ + t];
        __syncthreads();
        const int f = t & 255, q = t >> 8;
        const float* wp = Wd + (q * 128) * 256 + f;
        const float* hp = sdh + q * 128;
        float a0 = 0.f, a1 = 0.f, a2 = 0.f, a3 = 0.f;
#pragma unroll 8
        for (int d = 0; d < 128; d += 4) {
            a0 += hp[d]     * wp[(d)     * 256];
            a1 += hp[d + 1] * wp[(d + 1) * 256];
            a2 += hp[d + 2] * wp[(d + 2) * 256];
            a3 += hp[d + 3] * wp[(d + 3) * 256];
        }
        part[q][f] = (a0 + a1) + (a2 + a3);
        __syncthreads();
        if (t < 256) {
            float v = part[0][t] + part[1][t] + part[2][t] + part[3][t] + bd[t] + be[t];
            g_dw[b * 256 + t] = make_float2(v, Wa[t]);
        }
    }
}

// ---------------------------------------------------------------------------
// k_scores: 64-row compacted tile, fp16 HMMA + fused tanh/exp/context epilogue
//   A fp32 values teed into smem stage during prefetch; epilogue reads smem
// ---------------------------------------------------------------------------
static __device__ __forceinline__ void loadB(unsigned sb, int c, int tid) {
#pragma unroll
    for (int i = 0; i < 4; ++i) {
        int slot = tid + i * 256;
        cp16(sb + OBI(c & 1) + (unsigned)slot * 16u, &g_Bt[c][slot * 16]);
    }
    CP_COMMIT();
}
static __device__ __forceinline__ void cvtstore(unsigned dst, float4 v0, float4 v1) {
    float vf[8] = {v0.x, v0.y, v0.z, v0.w, v1.x, v1.y, v1.z, v1.w};
    unsigned hu[4];
#pragma unroll
    for (int q = 0; q < 4; ++q) {
        __half2 hp = __halves2half2(__float2half_rn(vf[2 * q]),
                                    __float2half_rn(vf[2 * q + 1]));
        hu[q] = *(unsigned*)&hp;
    }
    asm volatile("st.shared.v4.b32 [%0], {%1,%2,%3,%4};"
                 :: "r"(dst), "r"(hu[0]), "r"(hu[1]), "r"(hu[2]), "r"(hu[3]));
}
static __device__ __forceinline__ void stg_stage(unsigned dst, float4 v0, float4 v1) {
    asm volatile("st.shared.v4.b32 [%0], {%1,%2,%3,%4};"
                 :: "r"(dst), "f"(v0.x), "f"(v0.y), "f"(v0.z), "f"(v0.w));
    asm volatile("st.shared.v4.b32 [%0], {%1,%2,%3,%4};"
                 :: "r"(dst + 16u), "f"(v1.x), "f"(v1.y), "f"(v1.z), "f"(v1.w));
}

__global__ __launch_bounds__(256, 2)
void k_scores(const float* __restrict__ enc) {
    const int b = blockIdx.x >> 6, tt = blockIdx.x & 63;
    const int cnt = g_cnt[b];
    const int tid = threadIdx.x;
    if (tt * MT >= cnt) return;                       // inactive: nothing to do

    extern __shared__ __align__(16) unsigned char sm[];
    const unsigned sb = s2u(sm);
    const int lane = tid & 31, w = tid >> 5;
    const int wr = w & 1, wc = w >> 1;

    // this thread's A slice: row r_, cols [s_*8, s_*8+8) of each 32-wide chunk
    const int r_ = tid >> 2, s_ = tid & 3;
    const int j = tt * MT + r_;
    const int row = g_idx[b * S_ + min(j, cnt - 1)];
    const float4* ap = (const float4*)(enc + ((size_t)b * S_ + row) * 256 + s_ * 8);
    const unsigned adst = (unsigned)(((r_ >> 4) * 2 + (s_ >> 1)) * 512 +
                                     (s_ & 1) * 256 + (r_ & 15) * 16);
    const unsigned sdst = (unsigned)(r_ * 1024 + s_ * 32);   // fp32 stage base (row stride 1KB)

    loadB(sb, 0, tid);
    ((float2*)(sm + ODW))[tid] = g_dw[b * 256 + tid];

    float4 r0 = ap[0], r1 = ap[1];
    cvtstore(sb + OAI(0) + adst, r0, r1);
    stg_stage(sb + OST + sdst, r0, r1);
    CP_WAIT0();

    float acc[2][8][4];
#pragma unroll
    for (int mi = 0; mi < 2; ++mi)
#pragma unroll
        for (int ni = 0; ni < 8; ++ni)
#pragma unroll
            for (int q = 0; q < 4; ++q) acc[mi][ni][q] = 0.f;

    const unsigned a_lo = (unsigned)((lane & 15) * 16 + (lane >> 4) * 256);
    const unsigned b_lo = (unsigned)((lane & 7) * 16 + ((lane >> 4) & 1) * 128 +
                                     ((lane >> 3) & 1) * 256);

#pragma unroll 1
    for (int c = 0; c < 8; ++c) {
        const int buf = c & 1;
        __syncthreads();
        if (c < 7) {
            loadB(sb, c + 1, tid);
            r0 = ap[(c + 1) * 8];
            r1 = ap[(c + 1) * 8 + 1];
        }
        const unsigned ah_b = sb + OAI(buf) + a_lo;
        const unsigned bh_b = sb + OBI(buf) + b_lo;
#pragma unroll
        for (int ks = 0; ks < 2; ++ks) {
            unsigned af[2][4], bh[8][2];
#pragma unroll
            for (int mi = 0; mi < 2; ++mi)
                LDM4(af[mi], ah_b + (unsigned)(((wr * 2 + mi) * 2 + ks) * 512));
#pragma unroll
            for (int p = 0; p < 4; ++p) {
                const unsigned blk = (unsigned)(((wc * 4 + p) * 2 + ks) * 512);
                unsigned r4[4];
                LDM4(r4, bh_b + blk);
                bh[2 * p][0] = r4[0]; bh[2 * p][1] = r4[1];
                bh[2 * p + 1][0] = r4[2]; bh[2 * p + 1][1] = r4[3];
            }
#pragma unroll
            for (int mi = 0; mi < 2; ++mi)
#pragma unroll
                for (int ni = 0; ni < 8; ++ni)
                    MMAH(acc[mi][ni], af[mi], bh[ni][0], bh[ni][1]);
        }
        if (c < 7) {
            cvtstore(sb + OAI(buf ^ 1) + adst, r0, r1);
            stg_stage(sb + OST + sdst + (unsigned)(c + 1) * 128u, r0, r1);
            CP_WAIT0();
        }
    }

    // ---- Epilogue 1: score partials = sum_cols Wa * tanh(dpe + v) ----
    const float2* sdw = (const float2*)(sm + ODW);
    float* red = (float*)(sm + OBI(0));
#pragma unroll
    for (int mi = 0; mi < 2; ++mi) {
        float p0 = 0.f, p1 = 0.f;
#pragma unroll
        for (int ni = 0; ni < 8; ++ni) {
            int cc = wc * 64 + ni * 8 + 2 * (lane & 3);
            float2 w0 = sdw[cc], w1 = sdw[cc + 1];
            p0 += w0.y * tanha(acc[mi][ni][0] + w0.x) +
                  w1.y * tanha(acc[mi][ni][1] + w1.x);
            p1 += w0.y * tanha(acc[mi][ni][2] + w0.x) +
                  w1.y * tanha(acc[mi][ni][3] + w1.x);
        }
        p0 += __shfl_xor_sync(~0u, p0, 1); p0 += __shfl_xor_sync(~0u, p0, 2);
        p1 += __shfl_xor_sync(~0u, p1, 1); p1 += __shfl_xor_sync(~0u, p1, 2);
        if ((lane & 3) == 0) {
            int r = wr * 32 + mi * 16 + (lane >> 2);
            red[r * 5 + wc] = p0;
            red[(r + 8) * 5 + wc] = p1;
        }
    }
    __syncthreads();
    // ---- Epilogue 2: e = exp(score) (safe: |score| <= ~13), store ----
    float* se = (float*)(sm + OSE);
    if (tid < MT) {
        float s = red[tid * 5] + red[tid * 5 + 1] + red[tid * 5 + 2] + red[tid * 5 + 3];
        float e = (tt * MT + tid < cnt) ? __expf(s) : 0.f;
        se[tid] = e;
        g_scores[b * S_ + tt * MT + tid] = e;
    }
    __syncthreads();
    if (tid < 32) {                                   // tile sum of e
        float v = se[tid] + se[tid + 32];
#pragma unroll
        for (int o = 16; o; o >>= 1) v += __shfl_xor_sync(~0u, v, o);
        if (tid == 0) g_esum[b * 64 + tt] = v;
    }
    // ---- Epilogue 3: ctx partial = sum_r e[r] * A_stage[r,:] (pure smem) ----
    {
        const int c4 = tid & 63, rg = tid >> 6;
        const float4* sf = (const float4*)(sm + OST);
        float4 a4 = make_float4(0.f, 0.f, 0.f, 0.f);
#pragma unroll 4
        for (int i = 0; i < 16; ++i) {
            int r = rg * 16 + i;
            float wv = se[r];
            float4 ev = sf[r * 64 + c4];
            a4.x += wv * ev.x; a4.y += wv * ev.y; a4.z += wv * ev.z; a4.w += wv * ev.w;
        }
        float4* sr = (float4*)(sm + OAI(0));
        sr[rg * 64 + c4] = a4;
        __syncthreads();
        if (tid < 64) {
            float4 q0 = sr[tid], q1 = sr[64 + tid], q2 = sr[128 + tid], q3 = sr[192 + tid];
            float4 o;
            o.x = q0.x + q1.x + q2.x + q3.x;
            o.y = q0.y + q1.y + q2.y + q3.y;
            o.z = q0.z + q1.z + q2.z + q3.z;
            o.w = q0.w + q1.w + q2.w + q3.w;
            ((float4*)g_cpart)[((size_t)b * 64 + tt) * 64 + tid] = o;
        }
    }
}

// ---------------------------------------------------------------------------
// k_finish: per batch: sum active tiles -> ctx = acc/sum; attn scatter = e/sum
// ---------------------------------------------------------------------------
__global__ __launch_bounds__(1024)
void k_finish(float* __restrict__ ctx, float* __restrict__ attn) {
    const int b = blockIdx.x, t = threadIdx.x;
    const int cnt = g_cnt[b];
    const int ntiles = (cnt + MT - 1) / MT;           // only active tiles
    __shared__ float s_e[64];
    __shared__ float s_inv;
    if (t < 64) s_e[t] = (t < ntiles) ? g_esum[b * 64 + t] : 0.f;
    __syncthreads();
    if (t < 32) {
        float v = s_e[t] + s_e[t + 32];
#pragma unroll
        for (int o = 16; o; o >>= 1) v += __shfl_xor_sync(~0u, v, o);
        if (t == 0) s_inv = 1.f / v;
    }
    __syncthreads();
    const float inv = s_inv;
    if (t < 256) {
        const float* cp = g_cpart + (size_t)b * 64 * 256 + t;
        float a0 = 0.f, a1 = 0.f, a2 = 0.f, a3 = 0.f;
        int t2 = 0;
        for (; t2 + 4 <= ntiles; t2 += 4) {
            a0 += cp[(t2)     * 256];
            a1 += cp[(t2 + 1) * 256];
            a2 += cp[(t2 + 2) * 256];
            a3 += cp[(t2 + 3) * 256];
        }
        for (; t2 < ntiles; ++t2) a0 += cp[t2 * 256];
        ctx[b * 256 + t] = ((a0 + a1) + (a2 + a3)) * inv;
    }
    for (int j = t; j < cnt; j += 1024)
        attn[b * S_ + g_idx[b * S_ + j]] = g_scores[b * S_ + j] * inv;
}

// ---------------------------------------------------------------------------
extern "C" void kernel_launch(void* const* d_in, const int* in_sizes, int n_in,
                              void* d_out, int out_size) {
    const float* dh   = (const float*)d_in[0];
    const float* enc  = (const float*)d_in[1];
    const int*   mask = (const int*)  d_in[2];
    const float* Wd   = (const float*)d_in[3];
    const float* bd   = (const float*)d_in[4];
    const float* We   = (const float*)d_in[5];
    const float* be   = (const float*)d_in[6];
    const float* Wa   = (const float*)d_in[7];
    // d_in[8] = ba: uniform shift on scores, cancels in softmax

    float* out  = (float*)d_out;
    float* ctx  = out;
    float* attn = out + B_ * ENC_;

    cudaFuncSetAttribute(k_scores, cudaFuncAttributeMaxDynamicSharedMemorySize, SMEM_BYTES);

    k_pre<<<192, 1024>>>(mask, attn, We, dh, Wd, bd, be, Wa);
    k_scores<<<(B_ * S_) / MT, 256, SMEM_BYTES>>>(enc);
    k_finish<<<B_, 1024>>>(ctx, attn);
}